// round 10
// baseline (speedup 1.0000x reference)
#include <cuda_runtime.h>
#include <cuda_fp16.h>
#include <cstdint>

#define LL 2048
#define BB 32
#define HH 1024
#define MM (LL*BB)

// ---------------- device scratch ----------------
__device__ __half g_ah[(size_t)MM*HH];   // enc fp16, k-permuted within k16 windows
__device__ __half g_bh[(size_t)HH*HH];   // w1 fp16, same permutation
__device__ float2 g_pstP[(HH/2)*BB];     // (pst[2np][b], pst[2np+1][b]), bias folded
__device__ float g_spart[2*MM];          // score partials per N-half, [half][l*B+b]
__device__ float g_cpart[32*BB*HH];      // context partials

// ---------------- PTX helpers ----------------
__device__ __forceinline__ uint32_t smem_u32(const void* p){
    uint32_t a;
    asm("{ .reg .u64 t; cvta.to.shared.u64 t, %1; cvt.u32.u64 %0, t; }" : "=r"(a) : "l"(p));
    return a;
}
__device__ __forceinline__ void cp16(uint32_t dst, const void* src){
    asm volatile("cp.async.ca.shared.global [%0], [%1], 16;" :: "r"(dst), "l"(src));
}
__device__ __forceinline__ void cp_commit(){ asm volatile("cp.async.commit_group;" ::: "memory"); }
__device__ __forceinline__ void cp_wait2(){ asm volatile("cp.async.wait_group 2;" ::: "memory"); }
__device__ __forceinline__ void cp_wait0(){ asm volatile("cp.async.wait_group 0;" ::: "memory"); }
__device__ __forceinline__ void mma_f16(float* c, uint32_t a0, uint32_t a1, uint32_t a2, uint32_t a3,
                                        uint32_t b0, uint32_t b1){
    asm volatile("mma.sync.aligned.m16n8k16.row.col.f32.f16.f16.f32 "
        "{%0,%1,%2,%3}, {%4,%5,%6,%7}, {%8,%9}, {%0,%1,%2,%3};"
        : "+f"(c[0]), "+f"(c[1]), "+f"(c[2]), "+f"(c[3])
        : "r"(a0), "r"(a1), "r"(a2), "r"(a3), "r"(b0), "r"(b1));
}
// pair tanh via f16x2 MUFU
__device__ __forceinline__ float2 tanh2(float x0, float x1){
    uint32_t h2, t2;
    asm("cvt.rn.f16x2.f32 %0, %1, %2;" : "=r"(h2) : "f"(x1), "f"(x0));
    asm("tanh.approx.f16x2 %0, %1;" : "=r"(t2) : "r"(h2));
    float r0, r1;
    asm("{.reg .b16 l, h;\n mov.b32 {l, h}, %2;\n cvt.f32.f16 %0, l;\n cvt.f32.f16 %1, h;}"
        : "=f"(r0), "=f"(r1) : "r"(t2));
    return make_float2(r0, r1);
}

// ---------------- SMEM layout (per 128-thread CTA) ----------------
// k32 stage = [A0 4K][A1 4K][B0 2K][B1 2K] = 12288 B; 32B-row subtiles
// (same conflict-free phase layout as R8/R9). 4 stages.
#define STAGE_SZ 12288
#define OB       8192
#define O_RED    49152
#define SMEM_BYTES 53760     // 4*12288 + 128*9*4

// ---------------------------------------------------------------------------
// fp32 -> fp16, k-permuted within each k16 window:
// stored pos 4q+{0,1,2,3} <- orig k {2q, 2q+1, 2q+8, 2q+9}  (q = 0..3)
// Same permutation on A and B => sum over k unchanged.
// ---------------------------------------------------------------------------
__global__ void conv_half(const float* __restrict__ src, __half* __restrict__ dst){
    int t = blockIdx.x * 256 + threadIdx.x;
    int w = t & 63;             // k16 window
    int m = t >> 6;             // row
    const float* p = src + (size_t)m*HH + w*16;
    float4 x0 = *(const float4*)(p);
    float4 x1 = *(const float4*)(p + 4);
    float4 x2 = *(const float4*)(p + 8);
    float4 x3 = *(const float4*)(p + 12);
    float in[16] = {x0.x,x0.y,x0.z,x0.w, x1.x,x1.y,x1.z,x1.w,
                    x2.x,x2.y,x2.z,x2.w, x3.x,x3.y,x3.z,x3.w};
    uint32_t o[8];
    #pragma unroll
    for (int q = 0; q < 4; ++q){
        __half2 lo = __floats2half2_rn(in[2*q],     in[2*q + 1]);
        __half2 hi = __floats2half2_rn(in[2*q + 8], in[2*q + 9]);
        o[2*q]     = *(uint32_t*)&lo;
        o[2*q + 1] = *(uint32_t*)&hi;
    }
    uint4* d = (uint4*)(dst + (size_t)m*HH + w*16);
    d[0] = make_uint4(o[0], o[1], o[2], o[3]);
    d[1] = make_uint4(o[4], o[5], o[6], o[7]);
}

// ---------------------------------------------------------------------------
// pstP[np*32+b] = (pst[2np][b], pst[2np+1][b]); exact fp32
// ---------------------------------------------------------------------------
__global__ void pstT_kernel(const float* __restrict__ state, const float* __restrict__ w2,
                            const float* __restrict__ w1b, const float* __restrict__ w2b){
    int gw = (blockIdx.x * blockDim.x + threadIdx.x) >> 5;
    int lane = threadIdx.x & 31;
    if (gw >= (HH/2)*(BB/2)) return;
    int np = gw >> 4;
    int b0 = (gw & 15) * 2;
    int n0 = np * 2;
    const float* w0 = w2 + (size_t)n0 * HH;
    const float* w1r = w2 + (size_t)(n0+1) * HH;
    const float* s0 = state + b0*HH;
    const float* s1 = state + (b0+1)*HH;
    float a00=0.f, a01=0.f, a10=0.f, a11=0.f;
    #pragma unroll 4
    for (int h = lane; h < HH; h += 32){
        float x0 = s0[h], x1 = s1[h];
        float u = w0[h], w = w1r[h];
        a00 += u*x0; a01 += u*x1;
        a10 += w*x0; a11 += w*x1;
    }
    #pragma unroll
    for (int o = 16; o; o >>= 1){
        a00 += __shfl_xor_sync(~0u, a00, o);
        a01 += __shfl_xor_sync(~0u, a01, o);
        a10 += __shfl_xor_sync(~0u, a10, o);
        a11 += __shfl_xor_sync(~0u, a11, o);
    }
    if (lane == 0){
        float bias0 = w1b[n0] + w2b[n0];
        float bias1 = w1b[n0+1] + w2b[n0+1];
        g_pstP[np*BB + b0]   = make_float2(a00 + bias0, a10 + bias1);
        g_pstP[np*BB + b0+1] = make_float2(a01 + bias0, a11 + bias1);
    }
}

// ---------------------------------------------------------------------------
// cp.async one k32 stage (128 threads): A 128x64B + B 64x64B as k16 subtiles.
// s encodes (nt, kt32): kt32 = s & 31, nt = s >> 5 (64-wide N tiles).
// ---------------------------------------------------------------------------
__device__ __forceinline__ void cp_stage(uint32_t sb, int m0, int nbase, int s, int tid){
    int slot = s & 3;
    int kt = s & 31;
    int n0 = nbase + ((s >> 5) << 6);
    uint32_t base = sb + slot*STAGE_SZ;
    // A: row = tid
    const __half* asrc = g_ah + (size_t)(m0 + tid)*HH + kt*32;
    uint32_t adst = base + tid*32;
    cp16(adst,             asrc);
    cp16(adst + 16,        asrc + 8);
    cp16(adst + 4096,      asrc + 16);
    cp16(adst + 4096 + 16, asrc + 24);
    // B: row = tid>>1, chunk = tid&1
    const __half* bsrc = g_bh + (size_t)(n0 + (tid>>1))*HH + kt*32 + (tid&1)*8;
    uint32_t bdst = base + OB + (tid>>1)*32 + (tid&1)*16;
    cp16(bdst,        bsrc);
    cp16(bdst + 2048, bsrc + 16);
    cp_commit();
}

// ---------------------------------------------------------------------------
// fused fp16 GEMM + tanh + v-dot
// CTA 128M x 64N (4 warps, 2M x 2N, warp tile 64x32); grid (512 m-tiles, 2 n-halves).
// 4 CTAs/SM -> 4 independent barrier domains overlap load/MMA phases.
// 256 k32 macro-stages (8 nt x 32 kt), 4 buffers, prefetch 3 ahead.
// ---------------------------------------------------------------------------
__global__ void __launch_bounds__(128, 4)
gemm_score(const float* __restrict__ v){
    extern __shared__ __align__(128) char smem[];
    uint32_t sb = smem_u32(smem);
    const int tid  = threadIdx.x;
    const int lane = tid & 31;
    const int wid  = tid >> 5;
    const int wm   = wid & 1;       // 2 M-bands of 64
    const int wn   = wid >> 1;      // 2 N-bands of 32
    const int m0   = blockIdx.x * 128;
    const int half = blockIdx.y;
    const int nbase = half * 512;

    float* red = (float*)(smem + O_RED);
    for (int i = tid; i < 128*9; i += 128) red[i] = 0.f;
    __syncthreads();

    const int r0  = wm*64 + (lane>>2);    // A row base
    const int t8  = (lane&3)*8;           // byte offset of lane's 4 halves
    const int nb0 = wn*32 + (lane>>2);    // B row base (within 64)

    float acc[4][4][4];
    #pragma unroll
    for (int a = 0; a < 4; a++)
        #pragma unroll
        for (int b = 0; b < 4; b++)
            #pragma unroll
            for (int c = 0; c < 4; c++) acc[a][b][c] = 0.f;

    cp_stage(sb, m0, nbase, 0, tid);
    cp_stage(sb, m0, nbase, 1, tid);
    cp_stage(sb, m0, nbase, 2, tid);

    for (int s = 0; s < 256; ++s){
        if (s < 253) cp_wait2(); else cp_wait0();
        __syncthreads();
        if (s + 3 < 256) cp_stage(sb, m0, nbase, s + 3, tid);

        const char* st = smem + (s&3)*STAGE_SZ;

        #pragma unroll
        for (int h = 0; h < 2; ++h){
            const char* sA = st + h*4096;
            const char* sB = st + OB + h*2048;

            uint2 Bu[4];
            #pragma unroll
            for (int nf = 0; nf < 4; ++nf)
                Bu[nf] = *(const uint2*)(sB + (nb0 + nf*8)*32 + t8);

            uint2 Alo[4], Ahi[4];
            #pragma unroll
            for (int mf = 0; mf < 4; ++mf){
                Alo[mf] = *(const uint2*)(sA + (r0 + mf*16    )*32 + t8);
                Ahi[mf] = *(const uint2*)(sA + (r0 + mf*16 + 8)*32 + t8);
            }

            #pragma unroll
            for (int mf = 0; mf < 4; ++mf)
                #pragma unroll
                for (int nf = 0; nf < 4; ++nf)
                    mma_f16(acc[mf][nf], Alo[mf].x, Ahi[mf].x, Alo[mf].y, Ahi[mf].y,
                            Bu[nf].x, Bu[nf].y);
        }

        if ((s & 31) == 31){
            // epilogue for nt = s>>5 (64 N columns)
            int nt = s >> 5;
            int npb = (nbase >> 1) + nt*32 + wn*16 + (lane&3);
            float2 vp[4], pstr[4][4];                   // pstr[bg][nf]
            #pragma unroll
            for (int nf = 0; nf < 4; ++nf){
                int np = npb + nf*4;
                vp[nf] = *(const float2*)(v + np*2);
                #pragma unroll
                for (int bg = 0; bg < 4; ++bg){
                    int b = (lane>>2) + bg*8;
                    pstr[bg][nf] = __ldg(&g_pstP[np*BB + b]);
                }
            }
            #pragma unroll
            for (int mf = 0; mf < 4; ++mf){
                #pragma unroll
                for (int hf = 0; hf < 2; ++hf){
                    int row = wm*64 + mf*16 + (lane>>2) + hf*8;
                    int bg  = (mf&1)*2 + hf;
                    float sacc = 0.f;
                    #pragma unroll
                    for (int nf = 0; nf < 4; ++nf){
                        float x0 = acc[mf][nf][hf*2 + 0] + pstr[bg][nf].x;
                        float x1 = acc[mf][nf][hf*2 + 1] + pstr[bg][nf].y;
                        float2 t = tanh2(x0, x1);
                        sacc = fmaf(vp[nf].x, t.x, fmaf(vp[nf].y, t.y, sacc));
                    }
                    red[row*9 + wn*4 + (lane&3)] += sacc;
                }
            }
            #pragma unroll
            for (int a = 0; a < 4; a++)
                #pragma unroll
                for (int b = 0; b < 4; b++)
                    #pragma unroll
                    for (int c = 0; c < 4; c++) acc[a][b][c] = 0.f;
        }
    }

    __syncthreads();
    {
        const float* r = red + tid*9;
        float s = 0.f;
        #pragma unroll
        for (int j = 0; j < 8; ++j) s += r[j];
        g_spart[half*MM + m0 + tid] = s;
    }
}

// ---------------------------------------------------------------------------
// softmax over L per batch column b (sums the 2 N-half partials);
// weights -> out + B*H, layout [l*B+b]
// ---------------------------------------------------------------------------
__global__ void softmax_kernel(float* __restrict__ out){
    __shared__ float sdata[256];
    int b = blockIdx.x;
    int tid = threadIdx.x;

    float mx = -1e30f;
    for (int l = tid; l < LL; l += 256){
        int i = l*BB + b;
        mx = fmaxf(mx, g_spart[i] + g_spart[MM + i]);
    }
    sdata[tid] = mx; __syncthreads();
    for (int s = 128; s > 0; s >>= 1){ if (tid < s) sdata[tid] = fmaxf(sdata[tid], sdata[tid+s]); __syncthreads(); }
    mx = sdata[0]; __syncthreads();

    float sum = 0.f;
    for (int l = tid; l < LL; l += 256){
        int i = l*BB + b;
        sum += __expf(g_spart[i] + g_spart[MM + i] - mx);
    }
    sdata[tid] = sum; __syncthreads();
    for (int s = 128; s > 0; s >>= 1){ if (tid < s) sdata[tid] += sdata[tid+s]; __syncthreads(); }
    float inv = 1.f / sdata[0];

    float* w = out + BB*HH;
    for (int l = tid; l < LL; l += 256){
        int i = l*BB + b;
        w[i] = __expf(g_spart[i] + g_spart[MM + i] - mx) * inv;
    }
}

// ---------------------------------------------------------------------------
// context: 32-way L-split partials, then reduce; float4 over H
// ---------------------------------------------------------------------------
__global__ void ctx_part(const float* __restrict__ enc, const float* __restrict__ wts){
    int s = blockIdx.x;
    int b = blockIdx.y;
    int t = threadIdx.x;
    const float4* e = (const float4*)enc;
    float4 acc = make_float4(0.f, 0.f, 0.f, 0.f);
    int l0 = s * 64;
    #pragma unroll 4
    for (int l = 0; l < 64; ++l){
        float w = wts[(l0 + l)*BB + b];
        float4 x = e[((size_t)(l0 + l)*BB + b)*256 + t];
        acc.x += w*x.x; acc.y += w*x.y; acc.z += w*x.z; acc.w += w*x.w;
    }
    ((float4*)g_cpart)[((size_t)s*BB + b)*256 + t] = acc;
}
__global__ void ctx_reduce(float* __restrict__ out){
    int b = blockIdx.x;
    int t = threadIdx.x;
    float4 acc = make_float4(0.f, 0.f, 0.f, 0.f);
    #pragma unroll
    for (int s = 0; s < 32; ++s){
        float4 x = ((const float4*)g_cpart)[((size_t)s*BB + b)*256 + t];
        acc.x += x.x; acc.y += x.y; acc.z += x.z; acc.w += x.w;
    }
    ((float4*)out)[b*256 + t] = acc;
}

// ---------------------------------------------------------------------------
// launch: out = [context (B*H) | att_weights (L*B)]
// ---------------------------------------------------------------------------
extern "C" void kernel_launch(void* const* d_in, const int* in_sizes, int n_in,
                              void* d_out, int out_size) {
    const float* enc = (const float*)d_in[0];
    const float* lds = (const float*)d_in[1];   // state = first B*H floats
    const float* w1w = (const float*)d_in[2];
    const float* w1b = (const float*)d_in[3];
    const float* w2w = (const float*)d_in[4];
    const float* w2b = (const float*)d_in[5];
    const float* vw  = (const float*)d_in[6];
    // v_b cancels under softmax

    float* out = (float*)d_out;

    static bool attr_set = false;
    if (!attr_set){
        cudaFuncSetAttribute(gemm_score, cudaFuncAttributeMaxDynamicSharedMemorySize, SMEM_BYTES);
        attr_set = true;
    }

    __half *ah, *bh;
    cudaGetSymbolAddress((void**)&ah, g_ah);
    cudaGetSymbolAddress((void**)&bh, g_bh);

    conv_half<<<MM*64/256, 256>>>(enc, ah);
    conv_half<<<HH*64/256, 256>>>(w1w, bh);
    pstT_kernel<<<(HH/2)*(BB/2)/8, 256>>>(lds, w2w, w1b, w2b);
    gemm_score<<<dim3(MM/128, 2), 128, SMEM_BYTES>>>(vw);
    softmax_kernel<<<BB, 256>>>(out);
    ctx_part<<<dim3(32, BB), 256>>>(enc, out + BB*HH);
    ctx_reduce<<<BB, 256>>>(out);
}

// round 11
// speedup vs baseline: 1.4743x; 1.4743x over previous
#include <cuda_runtime.h>
#include <cuda_fp16.h>
#include <cstdint>

#define LL 2048
#define BB 32
#define HH 1024
#define MM (LL*BB)

// ---------------- device scratch ----------------
__device__ __half g_ah[(size_t)MM*HH];   // enc fp16, k-permuted within k16 windows
__device__ __half g_bh[(size_t)HH*HH];   // w1 fp16, same permutation
__device__ float2 g_pstP[(HH/2)*BB];     // (pst[2np][b], pst[2np+1][b]), bias folded
__device__ float g_score[MM];            // scores [l*B+b]
__device__ float g_cpart[32*BB*HH];      // context partials

// ---------------- PTX helpers ----------------
__device__ __forceinline__ uint32_t smem_u32(const void* p){
    uint32_t a;
    asm("{ .reg .u64 t; cvta.to.shared.u64 t, %1; cvt.u32.u64 %0, t; }" : "=r"(a) : "l"(p));
    return a;
}
__device__ __forceinline__ void cp16(uint32_t dst, const void* src){
    asm volatile("cp.async.ca.shared.global [%0], [%1], 16;" :: "r"(dst), "l"(src));
}
__device__ __forceinline__ void cp_commit(){ asm volatile("cp.async.commit_group;" ::: "memory"); }
__device__ __forceinline__ void cp_wait2(){ asm volatile("cp.async.wait_group 2;" ::: "memory"); }
__device__ __forceinline__ void cp_wait0(){ asm volatile("cp.async.wait_group 0;" ::: "memory"); }
__device__ __forceinline__ void mma_f16(float* c, uint32_t a0, uint32_t a1, uint32_t a2, uint32_t a3,
                                        uint32_t b0, uint32_t b1){
    asm volatile("mma.sync.aligned.m16n8k16.row.col.f32.f16.f16.f32 "
        "{%0,%1,%2,%3}, {%4,%5,%6,%7}, {%8,%9}, {%0,%1,%2,%3};"
        : "+f"(c[0]), "+f"(c[1]), "+f"(c[2]), "+f"(c[3])
        : "r"(a0), "r"(a1), "r"(a2), "r"(a3), "r"(b0), "r"(b1));
}
// pair tanh via f16x2 MUFU
__device__ __forceinline__ float2 tanh2(float x0, float x1){
    uint32_t h2, t2;
    asm("cvt.rn.f16x2.f32 %0, %1, %2;" : "=r"(h2) : "f"(x1), "f"(x0));
    asm("tanh.approx.f16x2 %0, %1;" : "=r"(t2) : "r"(h2));
    float r0, r1;
    asm("{.reg .b16 l, h;\n mov.b32 {l, h}, %2;\n cvt.f32.f16 %0, l;\n cvt.f32.f16 %1, h;}"
        : "=f"(r0), "=f"(r1) : "r"(t2));
    return make_float2(r0, r1);
}

// ---------------- SMEM layout ----------------
// k32 stage = [A0 4K][A1 4K][B0 4K][B1 4K] = 16384 B; 32B-row subtiles
// (same conflict-free phase layout as R8/R9). 4 stages.
#define STAGE_SZ 16384
#define OB       8192
#define O_RED    65536
#define SMEM_BYTES 74240     // 4*16384 + 128*17*4

// ---------------------------------------------------------------------------
// fp32 -> fp16, k-permuted within each k16 window:
// stored pos 4q+{0,1,2,3} <- orig k {2q, 2q+1, 2q+8, 2q+9}  (q = 0..3)
// Same permutation on A and B => sum over k unchanged.
// ---------------------------------------------------------------------------
__global__ void conv_half(const float* __restrict__ src, __half* __restrict__ dst){
    int t = blockIdx.x * 256 + threadIdx.x;
    int w = t & 63;             // k16 window
    int m = t >> 6;             // row
    const float* p = src + (size_t)m*HH + w*16;
    float4 x0 = *(const float4*)(p);
    float4 x1 = *(const float4*)(p + 4);
    float4 x2 = *(const float4*)(p + 8);
    float4 x3 = *(const float4*)(p + 12);
    float in[16] = {x0.x,x0.y,x0.z,x0.w, x1.x,x1.y,x1.z,x1.w,
                    x2.x,x2.y,x2.z,x2.w, x3.x,x3.y,x3.z,x3.w};
    uint32_t o[8];
    #pragma unroll
    for (int q = 0; q < 4; ++q){
        __half2 lo = __floats2half2_rn(in[2*q],     in[2*q + 1]);
        __half2 hi = __floats2half2_rn(in[2*q + 8], in[2*q + 9]);
        o[2*q]     = *(uint32_t*)&lo;
        o[2*q + 1] = *(uint32_t*)&hi;
    }
    uint4* d = (uint4*)(dst + (size_t)m*HH + w*16);
    d[0] = make_uint4(o[0], o[1], o[2], o[3]);
    d[1] = make_uint4(o[4], o[5], o[6], o[7]);
}

// ---------------------------------------------------------------------------
// pstP[np*32+b] = (pst[2np][b], pst[2np+1][b]); exact fp32
// ---------------------------------------------------------------------------
__global__ void pstT_kernel(const float* __restrict__ state, const float* __restrict__ w2,
                            const float* __restrict__ w1b, const float* __restrict__ w2b){
    int gw = (blockIdx.x * blockDim.x + threadIdx.x) >> 5;
    int lane = threadIdx.x & 31;
    if (gw >= (HH/2)*(BB/2)) return;
    int np = gw >> 4;
    int b0 = (gw & 15) * 2;
    int n0 = np * 2;
    const float* w0 = w2 + (size_t)n0 * HH;
    const float* w1r = w2 + (size_t)(n0+1) * HH;
    const float* s0 = state + b0*HH;
    const float* s1 = state + (b0+1)*HH;
    float a00=0.f, a01=0.f, a10=0.f, a11=0.f;
    #pragma unroll 4
    for (int h = lane; h < HH; h += 32){
        float x0 = s0[h], x1 = s1[h];
        float u = w0[h], w = w1r[h];
        a00 += u*x0; a01 += u*x1;
        a10 += w*x0; a11 += w*x1;
    }
    #pragma unroll
    for (int o = 16; o; o >>= 1){
        a00 += __shfl_xor_sync(~0u, a00, o);
        a01 += __shfl_xor_sync(~0u, a01, o);
        a10 += __shfl_xor_sync(~0u, a10, o);
        a11 += __shfl_xor_sync(~0u, a11, o);
    }
    if (lane == 0){
        float bias0 = w1b[n0] + w2b[n0];
        float bias1 = w1b[n0+1] + w2b[n0+1];
        g_pstP[np*BB + b0]   = make_float2(a00 + bias0, a10 + bias1);
        g_pstP[np*BB + b0+1] = make_float2(a01 + bias0, a11 + bias1);
    }
}

// ---------------------------------------------------------------------------
// cp.async one k32 stage: A 128x64B + B 128x64B as 2 k16 sub-tiles each.
// s encodes (nt, kt32): kt32 = s & 31, n0 = (s>>5)*128.
// ---------------------------------------------------------------------------
__device__ __forceinline__ void cp_stage(uint32_t sb, int m0, int s, int tid){
    int slot = s & 3;
    int kt = s & 31;
    int n0 = (s >> 5) << 7;
    uint32_t base = sb + slot*STAGE_SZ;
    int row = tid >> 1, c = tid & 1;
    const __half* asrc = g_ah + (size_t)(m0 + row)*HH + kt*32 + c*8;
    const __half* bsrc = g_bh + (size_t)(n0 + row)*HH + kt*32 + c*8;
    uint32_t adst = base + row*32 + c*16;
    uint32_t bdst = base + OB + row*32 + c*16;
    cp16(adst,        asrc);
    cp16(adst + 4096, asrc + 16);
    cp16(bdst,        bsrc);
    cp16(bdst + 4096, bsrc + 16);
    cp_commit();
}

// ---------------------------------------------------------------------------
// fused fp16 GEMM + tanh + v-dot
// CTA 128M x (8 x 128N); 8 warps (2M x 4N), warp tile 64x32, k32 macro-stages.
// Both k16-halves' fragments loaded up front (48 regs) -> 32-MMA tensor burst.
// Warp-staggered half order desynchronizes LDS bursts across warps.
// ---------------------------------------------------------------------------
__global__ void __launch_bounds__(256, 2)
gemm_score(const float* __restrict__ v){
    extern __shared__ __align__(128) char smem[];
    uint32_t sb = smem_u32(smem);
    const int tid  = threadIdx.x;
    const int lane = tid & 31;
    const int wid  = tid >> 5;
    const int wm   = wid & 1;       // 2 M-bands of 64
    const int wn   = wid >> 1;      // 4 N-bands of 32
    const int m0   = blockIdx.x * 128;
    const int hsel = wid & 1;       // stagger: odd warps do half1 first

    float* red = (float*)(smem + O_RED);
    for (int i = tid; i < 128*17; i += 256) red[i] = 0.f;
    __syncthreads();

    const int r0  = wm*64 + (lane>>2);    // A row base
    const int t8  = (lane&3)*8;           // byte offset of lane's 4 halves
    const int nb0 = wn*32 + (lane>>2);    // B row base

    float acc[4][4][4];
    #pragma unroll
    for (int a = 0; a < 4; a++)
        #pragma unroll
        for (int b = 0; b < 4; b++)
            #pragma unroll
            for (int c = 0; c < 4; c++) acc[a][b][c] = 0.f;

    cp_stage(sb, m0, 0, tid);
    cp_stage(sb, m0, 1, tid);
    cp_stage(sb, m0, 2, tid);

    for (int s = 0; s < 256; ++s){
        if (s < 253) cp_wait2(); else cp_wait0();
        __syncthreads();
        if (s + 3 < 256) cp_stage(sb, m0, s + 3, tid);

        const char* st = smem + (s&3)*STAGE_SZ;
        const char* sA0 = st + hsel*4096;
        const char* sB0 = st + OB + hsel*4096;
        const char* sA1 = st + (hsel^1)*4096;
        const char* sB1 = st + OB + (hsel^1)*4096;

        // ---- load ALL fragments for both halves (B0, A0, B1, A1) ----
        uint2 Bu0[4], Bu1[4], Alo0[4], Ahi0[4], Alo1[4], Ahi1[4];
        #pragma unroll
        for (int nf = 0; nf < 4; ++nf)
            Bu0[nf] = *(const uint2*)(sB0 + (nb0 + nf*8)*32 + t8);
        #pragma unroll
        for (int mf = 0; mf < 4; ++mf){
            Alo0[mf] = *(const uint2*)(sA0 + (r0 + mf*16    )*32 + t8);
            Ahi0[mf] = *(const uint2*)(sA0 + (r0 + mf*16 + 8)*32 + t8);
        }
        #pragma unroll
        for (int nf = 0; nf < 4; ++nf)
            Bu1[nf] = *(const uint2*)(sB1 + (nb0 + nf*8)*32 + t8);
        #pragma unroll
        for (int mf = 0; mf < 4; ++mf){
            Alo1[mf] = *(const uint2*)(sA1 + (r0 + mf*16    )*32 + t8);
            Ahi1[mf] = *(const uint2*)(sA1 + (r0 + mf*16 + 8)*32 + t8);
        }

        // ---- 32 back-to-back MMAs ----
        #pragma unroll
        for (int mf = 0; mf < 4; ++mf)
            #pragma unroll
            for (int nf = 0; nf < 4; ++nf)
                mma_f16(acc[mf][nf], Alo0[mf].x, Ahi0[mf].x, Alo0[mf].y, Ahi0[mf].y,
                        Bu0[nf].x, Bu0[nf].y);
        #pragma unroll
        for (int mf = 0; mf < 4; ++mf)
            #pragma unroll
            for (int nf = 0; nf < 4; ++nf)
                mma_f16(acc[mf][nf], Alo1[mf].x, Ahi1[mf].x, Alo1[mf].y, Ahi1[mf].y,
                        Bu1[nf].x, Bu1[nf].y);

        if ((s & 31) == 31){
            // epilogue for nt = s>>5 (N columns n0t..n0t+127)
            int n0t = (s >> 5) << 7;
            int npb = (n0t >> 1) + wn*16 + (lane&3);
            float2 vp[4], pstr[4][4];                   // pstr[bg][nf]
            #pragma unroll
            for (int nf = 0; nf < 4; ++nf){
                int np = npb + nf*4;
                vp[nf] = *(const float2*)(v + np*2);
                #pragma unroll
                for (int bg = 0; bg < 4; ++bg){
                    int b = (lane>>2) + bg*8;
                    pstr[bg][nf] = __ldg(&g_pstP[np*BB + b]);
                }
            }
            #pragma unroll
            for (int mf = 0; mf < 4; ++mf){
                #pragma unroll
                for (int half = 0; half < 2; ++half){
                    int row = wm*64 + mf*16 + (lane>>2) + half*8;
                    int bg  = (mf&1)*2 + half;
                    float sacc = 0.f;
                    #pragma unroll
                    for (int nf = 0; nf < 4; ++nf){
                        float x0 = acc[mf][nf][half*2 + 0] + pstr[bg][nf].x;
                        float x1 = acc[mf][nf][half*2 + 1] + pstr[bg][nf].y;
                        float2 t = tanh2(x0, x1);
                        sacc = fmaf(vp[nf].x, t.x, fmaf(vp[nf].y, t.y, sacc));
                    }
                    red[row*17 + wn*4 + (lane&3)] += sacc;
                }
            }
            #pragma unroll
            for (int a = 0; a < 4; a++)
                #pragma unroll
                for (int b = 0; b < 4; b++)
                    #pragma unroll
                    for (int c = 0; c < 4; c++) acc[a][b][c] = 0.f;
        }
    }

    __syncthreads();
    if (tid < 128){
        const float* r = red + tid*17;
        float s = 0.f;
        #pragma unroll
        for (int j = 0; j < 16; ++j) s += r[j];
        g_score[m0 + tid] = s;
    }
}

// ---------------------------------------------------------------------------
// softmax over L per batch column b; weights -> out + B*H, layout [l*B+b]
// ---------------------------------------------------------------------------
__global__ void softmax_kernel(float* __restrict__ out){
    __shared__ float sdata[256];
    int b = blockIdx.x;
    int tid = threadIdx.x;

    float mx = -1e30f;
    for (int l = tid; l < LL; l += 256) mx = fmaxf(mx, g_score[l*BB + b]);
    sdata[tid] = mx; __syncthreads();
    for (int s = 128; s > 0; s >>= 1){ if (tid < s) sdata[tid] = fmaxf(sdata[tid], sdata[tid+s]); __syncthreads(); }
    mx = sdata[0]; __syncthreads();

    float sum = 0.f;
    for (int l = tid; l < LL; l += 256) sum += __expf(g_score[l*BB + b] - mx);
    sdata[tid] = sum; __syncthreads();
    for (int s = 128; s > 0; s >>= 1){ if (tid < s) sdata[tid] += sdata[tid+s]; __syncthreads(); }
    float inv = 1.f / sdata[0];

    float* w = out + BB*HH;
    for (int l = tid; l < LL; l += 256)
        w[l*BB + b] = __expf(g_score[l*BB + b] - mx) * inv;
}

// ---------------------------------------------------------------------------
// context: 32-way L-split partials, then reduce; float4 over H
// ---------------------------------------------------------------------------
__global__ void ctx_part(const float* __restrict__ enc, const float* __restrict__ wts){
    int s = blockIdx.x;
    int b = blockIdx.y;
    int t = threadIdx.x;
    const float4* e = (const float4*)enc;
    float4 acc = make_float4(0.f, 0.f, 0.f, 0.f);
    int l0 = s * 64;
    #pragma unroll 4
    for (int l = 0; l < 64; ++l){
        float w = wts[(l0 + l)*BB + b];
        float4 x = e[((size_t)(l0 + l)*BB + b)*256 + t];
        acc.x += w*x.x; acc.y += w*x.y; acc.z += w*x.z; acc.w += w*x.w;
    }
    ((float4*)g_cpart)[((size_t)s*BB + b)*256 + t] = acc;
}
__global__ void ctx_reduce(float* __restrict__ out){
    int b = blockIdx.x;
    int t = threadIdx.x;
    float4 acc = make_float4(0.f, 0.f, 0.f, 0.f);
    #pragma unroll
    for (int s = 0; s < 32; ++s){
        float4 x = ((const float4*)g_cpart)[((size_t)s*BB + b)*256 + t];
        acc.x += x.x; acc.y += x.y; acc.z += x.z; acc.w += x.w;
    }
    ((float4*)out)[b*256 + t] = acc;
}

// ---------------------------------------------------------------------------
// launch: out = [context (B*H) | att_weights (L*B)]
// ---------------------------------------------------------------------------
extern "C" void kernel_launch(void* const* d_in, const int* in_sizes, int n_in,
                              void* d_out, int out_size) {
    const float* enc = (const float*)d_in[0];
    const float* lds = (const float*)d_in[1];   // state = first B*H floats
    const float* w1w = (const float*)d_in[2];
    const float* w1b = (const float*)d_in[3];
    const float* w2w = (const float*)d_in[4];
    const float* w2b = (const float*)d_in[5];
    const float* vw  = (const float*)d_in[6];
    // v_b cancels under softmax

    float* out = (float*)d_out;

    static bool attr_set = false;
    if (!attr_set){
        cudaFuncSetAttribute(gemm_score, cudaFuncAttributeMaxDynamicSharedMemorySize, SMEM_BYTES);
        attr_set = true;
    }

    __half *ah, *bh;
    cudaGetSymbolAddress((void**)&ah, g_ah);
    cudaGetSymbolAddress((void**)&bh, g_bh);

    conv_half<<<MM*64/256, 256>>>(enc, ah);
    conv_half<<<HH*64/256, 256>>>(w1w, bh);
    pstT_kernel<<<(HH/2)*(BB/2)/8, 256>>>(lds, w2w, w1b, w2b);
    gemm_score<<<MM/128, 256, SMEM_BYTES>>>(vw);
    softmax_kernel<<<BB, 256>>>(out);
    ctx_part<<<dim3(32, BB), 256>>>(enc, out + BB*HH);
    ctx_reduce<<<BB, 256>>>(out);
}